// round 1
// baseline (speedup 1.0000x reference)
#include <cuda_runtime.h>

#define NROWS 4096
#define KDIM  1024
#define NCOLS 4096

// Scratch for precomputed inverse row norms (no cudaMalloc allowed).
__device__ float g_inv_t[NROWS];
__device__ float g_inv_s[NROWS];

// ---------------------------------------------------------------------------
// Kernel 1: inverse L2 norm per row. One warp per row, float4 loads.
// sel == 0 -> write g_inv_t, sel == 1 -> write g_inv_s
// ---------------------------------------------------------------------------
__global__ void inv_norm_kernel(const float* __restrict__ x, int sel) {
    int warp = (blockIdx.x * blockDim.x + threadIdx.x) >> 5;
    int lane = threadIdx.x & 31;
    if (warp >= NROWS) return;

    const float4* row = (const float4*)(x + (size_t)warp * KDIM);
    float s = 0.f;
#pragma unroll
    for (int i = 0; i < (KDIM / 4) / 32; i++) {   // 8 float4 per lane
        float4 v = row[lane + i * 32];
        s = fmaf(v.x, v.x, s);
        s = fmaf(v.y, v.y, s);
        s = fmaf(v.z, v.z, s);
        s = fmaf(v.w, v.w, s);
    }
#pragma unroll
    for (int o = 16; o > 0; o >>= 1)
        s += __shfl_xor_sync(0xffffffffu, s, o);

    if (lane == 0) {
        float inv = rsqrtf(s);   // norms ~32 here; eps clamp in ref never binds
        if (sel == 0) g_inv_t[warp] = inv;
        else          g_inv_s[warp] = inv;
    }
}

// ---------------------------------------------------------------------------
// Kernel 2: C[i][j] = (t_i . s_j) * inv_t[i] * inv_s[j]
// Classic 128x128x16 blocked SGEMM, 256 threads, 8x8 per-thread microtile.
// Both operands are K-contiguous (A * B^T), so tiles are stored transposed
// into smem as [k][m] for broadcast-friendly fragment reads.
// ---------------------------------------------------------------------------
#define BM 128
#define BN 128
#define BK 16
#define TM 8
#define TN 8

__global__ __launch_bounds__(256, 2)
void cosine_gemm_kernel(const float* __restrict__ A,   // target [4096,1024]
                        const float* __restrict__ B,   // ss     [4096,1024]
                        float* __restrict__ C) {       // out [4096,4096]
    __shared__ float As[BK][BM];
    __shared__ float Bs[BK][BN];

    const int tid = threadIdx.x;
    const int tx  = tid & 15;        // 0..15 -> N direction
    const int ty  = tid >> 4;        // 0..15 -> M direction
    const int row0 = blockIdx.y * BM;
    const int col0 = blockIdx.x * BN;

    const float* Ab = A + (size_t)row0 * KDIM;
    const float* Bb = B + (size_t)col0 * KDIM;

    float acc[TM][TN];
#pragma unroll
    for (int i = 0; i < TM; i++)
#pragma unroll
        for (int j = 0; j < TN; j++)
            acc[i][j] = 0.f;

    for (int k0 = 0; k0 < KDIM; k0 += BK) {
        // Load 128x16 A and B tiles (2 float4 each per thread), transpose into smem.
#pragma unroll
        for (int i = 0; i < 2; i++) {
            int f  = tid + i * 256;      // 0..511 float4 slots
            int r  = f >> 2;             // row within tile 0..127
            int c4 = f & 3;              // which float4 of the 16-wide k-slab

            float4 va = *(const float4*)(Ab + (size_t)r * KDIM + k0 + c4 * 4);
            As[c4 * 4 + 0][r] = va.x;
            As[c4 * 4 + 1][r] = va.y;
            As[c4 * 4 + 2][r] = va.z;
            As[c4 * 4 + 3][r] = va.w;

            float4 vb = *(const float4*)(Bb + (size_t)r * KDIM + k0 + c4 * 4);
            Bs[c4 * 4 + 0][r] = vb.x;
            Bs[c4 * 4 + 1][r] = vb.y;
            Bs[c4 * 4 + 2][r] = vb.z;
            Bs[c4 * 4 + 3][r] = vb.w;
        }
        __syncthreads();

#pragma unroll
        for (int k = 0; k < BK; k++) {
            float a[TM], b[TN];
#pragma unroll
            for (int i = 0; i < 4; i++) {
                float4 v = *(const float4*)&As[k][ty * TM + i * 4 - ((i>=2)?8:0) + ((i>=2)?8:0)];
                // (kept simple below instead)
                (void)v; break;
            }
            // simple vectorized fragment loads
            {
                float4 a0 = *(const float4*)&As[k][ty * TM + 0];
                float4 a1 = *(const float4*)&As[k][ty * TM + 4];
                a[0]=a0.x; a[1]=a0.y; a[2]=a0.z; a[3]=a0.w;
                a[4]=a1.x; a[5]=a1.y; a[6]=a1.z; a[7]=a1.w;
                float4 b0 = *(const float4*)&Bs[k][tx * TN + 0];
                float4 b1 = *(const float4*)&Bs[k][tx * TN + 4];
                b[0]=b0.x; b[1]=b0.y; b[2]=b0.z; b[3]=b0.w;
                b[4]=b1.x; b[5]=b1.y; b[6]=b1.z; b[7]=b1.w;
            }
#pragma unroll
            for (int i = 0; i < TM; i++)
#pragma unroll
                for (int j = 0; j < TN; j++)
                    acc[i][j] = fmaf(a[i], b[j], acc[i][j]);
        }
        __syncthreads();
    }

    // Epilogue: scale by inverse norms, vectorized float4 stores.
    float ia[TM], ib[TN];
#pragma unroll
    for (int i = 0; i < TM; i++) ia[i] = g_inv_t[row0 + ty * TM + i];
#pragma unroll
    for (int j = 0; j < TN; j++) ib[j] = g_inv_s[col0 + tx * TN + j];

#pragma unroll
    for (int i = 0; i < TM; i++) {
        float* crow = C + (size_t)(row0 + ty * TM + i) * NCOLS + col0 + tx * TN;
        float4 o0, o1;
        o0.x = acc[i][0] * ia[i] * ib[0];
        o0.y = acc[i][1] * ia[i] * ib[1];
        o0.z = acc[i][2] * ia[i] * ib[2];
        o0.w = acc[i][3] * ia[i] * ib[3];
        o1.x = acc[i][4] * ia[i] * ib[4];
        o1.y = acc[i][5] * ia[i] * ib[5];
        o1.z = acc[i][6] * ia[i] * ib[6];
        o1.w = acc[i][7] * ia[i] * ib[7];
        *(float4*)(crow + 0) = o0;
        *(float4*)(crow + 4) = o1;
    }
}

// ---------------------------------------------------------------------------
extern "C" void kernel_launch(void* const* d_in, const int* in_sizes, int n_in,
                              void* d_out, int out_size) {
    const float* target = (const float*)d_in[0];
    const float* ss     = (const float*)d_in[1];
    float* out          = (float*)d_out;

    // 1 warp per row, 8 warps per block -> 512 blocks per matrix
    inv_norm_kernel<<<NROWS / 8, 256>>>(target, 0);
    inv_norm_kernel<<<NROWS / 8, 256>>>(ss, 1);

    dim3 grid(NCOLS / BN, NROWS / BM);   // 32 x 32
    cosine_gemm_kernel<<<grid, 256>>>(target, ss, out);
}

// round 3
// speedup vs baseline: 3.4614x; 3.4614x over previous
#include <cuda_runtime.h>
#include <cstdint>

#define NROWS 4096
#define KDIM  1024
#define NCOLS 4096

#define BM 128
#define BN 128
#define BK 32
#define STAGES 3
#define KITERS (KDIM / BK)          // 32

#define PAD    4
#define LDA    (BK + PAD)           // 36 words per smem row
#define AS_WORDS (BM * LDA)         // 4608
#define STAGE_WORDS (2 * AS_WORDS)  // 9216
#define SMEM_BYTES (STAGES * STAGE_WORDS * 4)   // 110592

// ---------------------------------------------------------------------------
// Device scratch: tf32-rounded copies + inverse row norms (no cudaMalloc).
// ---------------------------------------------------------------------------
__device__ float g_ta[NROWS * KDIM];    // 16 MB
__device__ float g_sa[NROWS * KDIM];    // 16 MB
__device__ float g_inv_t[NROWS];
__device__ float g_inv_s[NROWS];

// ---------------------------------------------------------------------------
// PTX helpers
// ---------------------------------------------------------------------------
__device__ __forceinline__ uint32_t smem_u32(const void* p) {
    uint32_t a;
    asm("{ .reg .u64 t; cvta.to.shared.u64 t, %1; cvt.u32.u64 %0, t; }" : "=r"(a) : "l"(p));
    return a;
}

#define CP_ASYNC16(dst, src) \
    asm volatile("cp.async.cg.shared.global [%0], [%1], 16;" :: "r"(dst), "l"(src) : "memory")
#define CP_COMMIT() asm volatile("cp.async.commit_group;" ::: "memory")
#define CP_WAIT(n)  asm volatile("cp.async.wait_group %0;" :: "n"(n) : "memory")

__device__ __forceinline__ void mma_tf32(float* c, const uint32_t* a, const uint32_t* b) {
    asm volatile(
        "mma.sync.aligned.m16n8k8.row.col.f32.tf32.tf32.f32 "
        "{%0, %1, %2, %3}, {%4, %5, %6, %7}, {%8, %9}, {%0, %1, %2, %3};"
        : "+f"(c[0]), "+f"(c[1]), "+f"(c[2]), "+f"(c[3])
        : "r"(a[0]), "r"(a[1]), "r"(a[2]), "r"(a[3]), "r"(b[0]), "r"(b[1]));
}

// ---------------------------------------------------------------------------
// Kernel 1: per-row inverse L2 norm (exact fp32) + tf32-rounded copy.
// 1 warp per row; rows 0..4095 = target, 4096..8191 = ss.
// ---------------------------------------------------------------------------
__global__ void norm_round_kernel(const float* __restrict__ t, const float* __restrict__ s) {
    int gw = (blockIdx.x * blockDim.x + threadIdx.x) >> 5;
    int lane = threadIdx.x & 31;
    if (gw >= 2 * NROWS) return;

    const float* src = (gw < NROWS) ? t : s;
    float* dst       = (gw < NROWS) ? g_ta : g_sa;
    float* invp      = (gw < NROWS) ? g_inv_t : g_inv_s;
    int row = (gw < NROWS) ? gw : gw - NROWS;

    const float4* rin  = (const float4*)(src + (size_t)row * KDIM);
    float4*       rout = (float4*)(dst + (size_t)row * KDIM);

    float acc = 0.f;
#pragma unroll
    for (int i = 0; i < (KDIM / 4) / 32; i++) {   // 8 float4 per lane
        float4 v = rin[lane + i * 32];
        acc = fmaf(v.x, v.x, acc);
        acc = fmaf(v.y, v.y, acc);
        acc = fmaf(v.z, v.z, acc);
        acc = fmaf(v.w, v.w, acc);
        float4 o;
        uint32_t u;
        asm("cvt.rna.tf32.f32 %0, %1;" : "=r"(u) : "f"(v.x)); o.x = __uint_as_float(u);
        asm("cvt.rna.tf32.f32 %0, %1;" : "=r"(u) : "f"(v.y)); o.y = __uint_as_float(u);
        asm("cvt.rna.tf32.f32 %0, %1;" : "=r"(u) : "f"(v.z)); o.z = __uint_as_float(u);
        asm("cvt.rna.tf32.f32 %0, %1;" : "=r"(u) : "f"(v.w)); o.w = __uint_as_float(u);
        rout[lane + i * 32] = o;
    }
#pragma unroll
    for (int o = 16; o > 0; o >>= 1)
        acc += __shfl_xor_sync(0xffffffffu, acc, o);
    if (lane == 0)
        invp[row] = rsqrtf(acc);   // norms ~32: eps clamp in ref never binds
}

// ---------------------------------------------------------------------------
// Kernel 2: tf32 mma.sync GEMM with fused cosine epilogue.
// C[i][j] = (t_i . s_j) * inv_t[i] * inv_s[j]
// CTA 128x128x32, 8 warps (2 m x 4 n), warp tile 64x32, m16n8k8 fragments.
// 3-stage cp.async pipeline; smem rows padded to 36 words (conflict-free LDS).
// ---------------------------------------------------------------------------
__global__ void __launch_bounds__(256, 2)
cosine_mma_kernel(const float* __restrict__ A,   // g_ta [4096,1024] (tf32 bits)
                  const float* __restrict__ B,   // g_sa [4096,1024] (tf32 bits)
                  float* __restrict__ C) {
    extern __shared__ float smem[];
    const uint32_t sbase = smem_u32(smem);

    const int tid  = threadIdx.x;
    const int wid  = tid >> 5;
    const int lane = tid & 31;
    const int g  = lane >> 2;      // 0..7
    const int tk = lane & 3;       // 0..3

    const int wm = wid & 1;        // 2 m-warps
    const int wn = wid >> 1;       // 4 n-warps
    const int mbase = wm * 64;
    const int nbase = wn * 32;

    const int row0 = blockIdx.y * BM;
    const int col0 = blockIdx.x * BN;

    const float* Ab = A + (size_t)row0 * KDIM;
    const float* Bb = B + (size_t)col0 * KDIM;

    float acc[4][4][4];
#pragma unroll
    for (int i = 0; i < 4; i++)
#pragma unroll
        for (int j = 0; j < 4; j++)
#pragma unroll
            for (int q = 0; q < 4; q++)
                acc[i][j][q] = 0.f;

    // ---- async stage loader: 16B chunks, 8 per thread ----
    auto issue_stage = [&](int s, int k0) {
        uint32_t sa = sbase + (uint32_t)(s * STAGE_WORDS) * 4u;
        uint32_t sb2 = sa + (uint32_t)AS_WORDS * 4u;
#pragma unroll
        for (int i = 0; i < 4; i++) {
            int c  = tid + i * 256;      // 0..1023
            int r  = c >> 3;
            int c4 = c & 7;
            CP_ASYNC16(sa  + (uint32_t)(r * LDA + c4 * 4) * 4u, Ab + (size_t)r * KDIM + k0 + c4 * 4);
            CP_ASYNC16(sb2 + (uint32_t)(r * LDA + c4 * 4) * 4u, Bb + (size_t)r * KDIM + k0 + c4 * 4);
        }
    };

    // prologue: STAGES-1 stages in flight
#pragma unroll
    for (int s = 0; s < STAGES - 1; s++) {
        issue_stage(s, s * BK);
        CP_COMMIT();
    }

    for (int it = 0; it < KITERS; it++) {
        CP_WAIT(STAGES - 2);
        __syncthreads();

        int nx = it + STAGES - 1;
        if (nx < KITERS) issue_stage(nx % STAGES, nx * BK);
        CP_COMMIT();

        const float* As = smem + (it % STAGES) * STAGE_WORDS;
        const float* Bs = As + AS_WORDS;

#pragma unroll
        for (int kk = 0; kk < BK / 8; kk++) {
            const int k8 = kk * 8;
            uint32_t a[4][4], b[4][2];
#pragma unroll
            for (int mt = 0; mt < 4; mt++) {
                const int m = mbase + mt * 16 + g;
                a[mt][0] = __float_as_uint(As[m * LDA + k8 + tk]);
                a[mt][1] = __float_as_uint(As[(m + 8) * LDA + k8 + tk]);
                a[mt][2] = __float_as_uint(As[m * LDA + k8 + tk + 4]);
                a[mt][3] = __float_as_uint(As[(m + 8) * LDA + k8 + tk + 4]);
            }
#pragma unroll
            for (int nt = 0; nt < 4; nt++) {
                const int n = nbase + nt * 8 + g;
                b[nt][0] = __float_as_uint(Bs[n * LDA + k8 + tk]);
                b[nt][1] = __float_as_uint(Bs[n * LDA + k8 + tk + 4]);
            }
#pragma unroll
            for (int mt = 0; mt < 4; mt++)
#pragma unroll
                for (int nt = 0; nt < 4; nt++)
                    mma_tf32(acc[mt][nt], a[mt], b[nt]);
        }
        __syncthreads();
    }

    // ---- epilogue: fold inverse norms, float2 stores ----
#pragma unroll
    for (int mt = 0; mt < 4; mt++) {
        const int r0 = row0 + mbase + mt * 16 + g;
        const int r1 = r0 + 8;
        const float ia0 = g_inv_t[r0];
        const float ia1 = g_inv_t[r1];
#pragma unroll
        for (int nt = 0; nt < 4; nt++) {
            const int col = col0 + nbase + nt * 8 + 2 * tk;
            const float ib0 = g_inv_s[col];
            const float ib1 = g_inv_s[col + 1];
            float2 o0, o1;
            o0.x = acc[mt][nt][0] * ia0 * ib0;
            o0.y = acc[mt][nt][1] * ia0 * ib1;
            o1.x = acc[mt][nt][2] * ia1 * ib0;
            o1.y = acc[mt][nt][3] * ia1 * ib1;
            *(float2*)(C + (size_t)r0 * NCOLS + col) = o0;
            *(float2*)(C + (size_t)r1 * NCOLS + col) = o1;
        }
    }
}

// ---------------------------------------------------------------------------
extern "C" void kernel_launch(void* const* d_in, const int* in_sizes, int n_in,
                              void* d_out, int out_size) {
    const float* target = (const float*)d_in[0];
    const float* ss     = (const float*)d_in[1];
    float* out          = (float*)d_out;

    norm_round_kernel<<<(2 * NROWS) / 8, 256>>>(target, ss);

    void* pa = nullptr; void* pb = nullptr;
    cudaGetSymbolAddress(&pa, g_ta);
    cudaGetSymbolAddress(&pb, g_sa);

    cudaFuncSetAttribute(cosine_mma_kernel, cudaFuncAttributeMaxDynamicSharedMemorySize, SMEM_BYTES);

    dim3 grid(NCOLS / BN, NROWS / BM);   // 32 x 32
    cosine_mma_kernel<<<grid, 256, SMEM_BYTES>>>((const float*)pa, (const float*)pb, out);
}

// round 4
// speedup vs baseline: 3.8759x; 1.1198x over previous
#include <cuda_runtime.h>
#include <cstdint>

#define NROWS 4096
#define KDIM  1024
#define NCOLS 4096

#define BM 128
#define BN 128
#define BK 32
#define STAGES 2
#define KITERS (KDIM / BK)          // 32

#define LDA    40                   // BK + 8 pad words: LDS.64 conflict-free
#define AS_WORDS (BM * LDA)         // 5120
#define STAGE_WORDS (2 * AS_WORDS)  // 10240
#define SMEM_BYTES (STAGES * STAGE_WORDS * 4)   // 81920

// ---------------------------------------------------------------------------
// Device scratch: tf32-rounded, K-permuted copies + inverse row norms.
// Within each K 8-group, element order is [0,4,1,5,2,6,3,7] so that a
// fragment pair (k, k+4) is contiguous (enables LDS.64 in the mainloop).
// ---------------------------------------------------------------------------
__device__ float g_ta[NROWS * KDIM];    // 16 MB
__device__ float g_sa[NROWS * KDIM];    // 16 MB
__device__ float g_inv_t[NROWS];
__device__ float g_inv_s[NROWS];

// ---------------------------------------------------------------------------
// PTX helpers
// ---------------------------------------------------------------------------
__device__ __forceinline__ uint32_t smem_u32(const void* p) {
    uint32_t a;
    asm("{ .reg .u64 t; cvta.to.shared.u64 t, %1; cvt.u32.u64 %0, t; }" : "=r"(a) : "l"(p));
    return a;
}

#define CP_ASYNC16(dst, src) \
    asm volatile("cp.async.cg.shared.global [%0], [%1], 16;" :: "r"(dst), "l"(src) : "memory")
#define CP_COMMIT() asm volatile("cp.async.commit_group;" ::: "memory")
#define CP_WAIT(n)  asm volatile("cp.async.wait_group %0;" :: "n"(n) : "memory")

__device__ __forceinline__ void mma_tf32(float* c, const uint32_t* a, const uint32_t* b) {
    asm volatile(
        "mma.sync.aligned.m16n8k8.row.col.f32.tf32.tf32.f32 "
        "{%0, %1, %2, %3}, {%4, %5, %6, %7}, {%8, %9}, {%0, %1, %2, %3};"
        : "+f"(c[0]), "+f"(c[1]), "+f"(c[2]), "+f"(c[3])
        : "r"(a[0]), "r"(a[1]), "r"(a[2]), "r"(a[3]), "r"(b[0]), "r"(b[1]));
}

__device__ __forceinline__ float tf32_rna(float x) {
    uint32_t u;
    asm("cvt.rna.tf32.f32 %0, %1;" : "=r"(u) : "f"(x));
    return __uint_as_float(u);
}

// ---------------------------------------------------------------------------
// Kernel 1: per-row inverse L2 norm (exact fp32) + tf32-rounded PERMUTED copy.
// 1 warp per row; rows 0..4095 = target, 4096..8191 = ss.
// Lane c holds float4 = original k[4c..4c+3]. Pair (2j, 2j+1) covers 8-group j:
//   even lane writes out float4 (lo.x, hi.x, lo.y, hi.y)  -> k {0,4,1,5}
//   odd  lane writes out float4 (lo.z, hi.z, lo.w, hi.w)  -> k {2,6,3,7}
// ---------------------------------------------------------------------------
__global__ void norm_round_kernel(const float* __restrict__ t, const float* __restrict__ s) {
    int gw = (blockIdx.x * blockDim.x + threadIdx.x) >> 5;
    int lane = threadIdx.x & 31;
    if (gw >= 2 * NROWS) return;

    const float* src = (gw < NROWS) ? t : s;
    float* dst       = (gw < NROWS) ? g_ta : g_sa;
    float* invp      = (gw < NROWS) ? g_inv_t : g_inv_s;
    int row = (gw < NROWS) ? gw : gw - NROWS;

    const float4* rin  = (const float4*)(src + (size_t)row * KDIM);
    float4*       rout = (float4*)(dst + (size_t)row * KDIM);

    float acc = 0.f;
#pragma unroll
    for (int i = 0; i < (KDIM / 4) / 32; i++) {   // 8 float4 per lane
        int c = lane + i * 32;
        float4 v = rin[c];
        acc = fmaf(v.x, v.x, acc);
        acc = fmaf(v.y, v.y, acc);
        acc = fmaf(v.z, v.z, acc);
        acc = fmaf(v.w, v.w, acc);

        float4 r;
        r.x = tf32_rna(v.x); r.y = tf32_rna(v.y);
        r.z = tf32_rna(v.z); r.w = tf32_rna(v.w);

        // exchange with partner lane (c parity == lane parity)
        float4 p;
        p.x = __shfl_xor_sync(0xffffffffu, r.x, 1);
        p.y = __shfl_xor_sync(0xffffffffu, r.y, 1);
        p.z = __shfl_xor_sync(0xffffffffu, r.z, 1);
        p.w = __shfl_xor_sync(0xffffffffu, r.w, 1);

        float4 o;
        if ((c & 1) == 0) {        // r = lo half, p = hi half
            o.x = r.x; o.y = p.x; o.z = r.y; o.w = p.y;
        } else {                   // p = lo half, r = hi half
            o.x = p.z; o.y = r.z; o.z = p.w; o.w = r.w;
        }
        rout[(c >> 1) * 2 + (c & 1)] = o;
    }
#pragma unroll
    for (int o = 16; o > 0; o >>= 1)
        acc += __shfl_xor_sync(0xffffffffu, acc, o);
    if (lane == 0)
        invp[row] = rsqrtf(acc);   // norms ~32: eps clamp in ref never binds
}

// ---------------------------------------------------------------------------
// Kernel 2: tf32 mma.sync GEMM with fused cosine epilogue.
// CTA 128x128x32, 8 warps (2 m x 4 n), warp tile 64x32, m16n8k8 fragments.
// 2-stage cp.async pipeline; permuted operands -> LDS.64 fragment loads.
// ---------------------------------------------------------------------------
__global__ void __launch_bounds__(256, 2)
cosine_mma_kernel(const float* __restrict__ A,   // g_ta (tf32 bits, K-permuted)
                  const float* __restrict__ B,   // g_sa (tf32 bits, K-permuted)
                  float* __restrict__ C) {
    extern __shared__ float smem[];
    const uint32_t sbase = smem_u32(smem);

    const int tid  = threadIdx.x;
    const int wid  = tid >> 5;
    const int lane = tid & 31;
    const int g  = lane >> 2;      // 0..7
    const int tk = lane & 3;       // 0..3

    const int wm = wid & 1;        // 2 m-warps
    const int wn = wid >> 1;       // 4 n-warps
    const int mbase = wm * 64;
    const int nbase = wn * 32;

    const int row0 = blockIdx.y * BM;
    const int col0 = blockIdx.x * BN;

    const float* Ab = A + (size_t)row0 * KDIM;
    const float* Bb = B + (size_t)col0 * KDIM;

    float acc[4][4][4];
#pragma unroll
    for (int i = 0; i < 4; i++)
#pragma unroll
        for (int j = 0; j < 4; j++)
#pragma unroll
            for (int q = 0; q < 4; q++)
                acc[i][j][q] = 0.f;

    // ---- async stage loader: 16B chunks, 8 per thread ----
    auto issue_stage = [&](int s, int k0) {
        uint32_t sa  = sbase + (uint32_t)(s * STAGE_WORDS) * 4u;
        uint32_t sb2 = sa + (uint32_t)AS_WORDS * 4u;
#pragma unroll
        for (int i = 0; i < 4; i++) {
            int c  = tid + i * 256;      // 0..1023
            int r  = c >> 3;
            int c4 = c & 7;
            CP_ASYNC16(sa  + (uint32_t)(r * LDA + c4 * 4) * 4u, Ab + (size_t)r * KDIM + k0 + c4 * 4);
            CP_ASYNC16(sb2 + (uint32_t)(r * LDA + c4 * 4) * 4u, Bb + (size_t)r * KDIM + k0 + c4 * 4);
        }
    };

    issue_stage(0, 0);
    CP_COMMIT();

    for (int it = 0; it < KITERS; it++) {
        CP_WAIT(0);
        __syncthreads();

        int nx = it + 1;
        if (nx < KITERS) {
            issue_stage(nx & 1, nx * BK);
            CP_COMMIT();
        }

        const float* As = smem + (it & 1) * STAGE_WORDS;
        const float* Bs = As + AS_WORDS;

#pragma unroll
        for (int kk = 0; kk < BK / 8; kk++) {
            const int kc = kk * 8 + 2 * tk;   // permuted: (k8+tk, k8+tk+4) contiguous
            uint32_t a[4][4], b[4][2];
#pragma unroll
            for (int mt = 0; mt < 4; mt++) {
                const int m = mbase + mt * 16 + g;
                float2 la = *(const float2*)&As[m * LDA + kc];
                float2 lb = *(const float2*)&As[(m + 8) * LDA + kc];
                a[mt][0] = __float_as_uint(la.x);
                a[mt][1] = __float_as_uint(lb.x);
                a[mt][2] = __float_as_uint(la.y);
                a[mt][3] = __float_as_uint(lb.y);
            }
#pragma unroll
            for (int nt = 0; nt < 4; nt++) {
                const int n = nbase + nt * 8 + g;
                float2 lb = *(const float2*)&Bs[n * LDA + kc];
                b[nt][0] = __float_as_uint(lb.x);
                b[nt][1] = __float_as_uint(lb.y);
            }
#pragma unroll
            for (int mt = 0; mt < 4; mt++)
#pragma unroll
                for (int nt = 0; nt < 4; nt++)
                    mma_tf32(acc[mt][nt], a[mt], b[nt]);
        }
        __syncthreads();
    }

    // ---- epilogue: fold inverse norms, float2 stores ----
#pragma unroll
    for (int mt = 0; mt < 4; mt++) {
        const int r0 = row0 + mbase + mt * 16 + g;
        const int r1 = r0 + 8;
        const float ia0 = g_inv_t[r0];
        const float ia1 = g_inv_t[r1];
#pragma unroll
        for (int nt = 0; nt < 4; nt++) {
            const int col = col0 + nbase + nt * 8 + 2 * tk;
            const float ib0 = g_inv_s[col];
            const float ib1 = g_inv_s[col + 1];
            float2 o0, o1;
            o0.x = acc[mt][nt][0] * ia0 * ib0;
            o0.y = acc[mt][nt][1] * ia0 * ib1;
            o1.x = acc[mt][nt][2] * ia1 * ib0;
            o1.y = acc[mt][nt][3] * ia1 * ib1;
            *(float2*)(C + (size_t)r0 * NCOLS + col) = o0;
            *(float2*)(C + (size_t)r1 * NCOLS + col) = o1;
        }
    }
}

// ---------------------------------------------------------------------------
extern "C" void kernel_launch(void* const* d_in, const int* in_sizes, int n_in,
                              void* d_out, int out_size) {
    const float* target = (const float*)d_in[0];
    const float* ss     = (const float*)d_in[1];
    float* out          = (float*)d_out;

    norm_round_kernel<<<(2 * NROWS) / 8, 256>>>(target, ss);

    void* pa = nullptr; void* pb = nullptr;
    cudaGetSymbolAddress(&pa, g_ta);
    cudaGetSymbolAddress(&pb, g_sa);

    cudaFuncSetAttribute(cosine_mma_kernel, cudaFuncAttributeMaxDynamicSharedMemorySize, SMEM_BYTES);

    dim3 grid(NCOLS / BN, NROWS / BM);   // 32 x 32
    cosine_mma_kernel<<<grid, 256, SMEM_BYTES>>>((const float*)pa, (const float*)pb, out);
}

// round 7
// speedup vs baseline: 6.7442x; 1.7400x over previous
#include <cuda_runtime.h>
#include <cuda_fp16.h>
#include <cstdint>

#define NROWS 4096
#define KDIM  1024
#define NCOLS 4096

#define BM 128
#define BN 128
#define BK 32
#define STAGES 4
#define KITERS (KDIM / BK)              // 32

#define NR16 (NROWS / 16)               // 256 row-groups
#define NKG  (KDIM / 16)                // 64 k16-groups

#define STAGE_BYTES 16384               // 8KB A + 8KB B, fragment-ordered
#define SMEM_BYTES (STAGES * STAGE_BYTES)   // 65536

// ---------------------------------------------------------------------------
// Device scratch: fp16 fragment-ordered copies + inverse row norms.
// Layout per matrix: [R=row/16][Kg=k/16][lane][uint4], uint4 = this lane's
// full m16n8k16 A-fragment: {h2(r=g,k=2tk..2tk+1), h2(r=g+8,k=2tk..2tk+1),
//                            h2(r=g,k=8+2tk..),    h2(r=g+8,k=8+2tk..)}
// where g=lane>>2, tk=lane&3.  8 MB per matrix.
// ---------------------------------------------------------------------------
__device__ uint4 g_pa[NR16 * NKG * 32];
__device__ uint4 g_pb[NR16 * NKG * 32];
__device__ float g_inv_t[NROWS];
__device__ float g_inv_s[NROWS];

// ---------------------------------------------------------------------------
// PTX helpers
// ---------------------------------------------------------------------------
__device__ __forceinline__ uint32_t smem_u32(const void* p) {
    uint32_t a;
    asm("{ .reg .u64 t; cvta.to.shared.u64 t, %1; cvt.u32.u64 %0, t; }" : "=r"(a) : "l"(p));
    return a;
}

// pack two floats into f16x2: lo -> low half, hi -> high half
__device__ __forceinline__ uint32_t pack_h2(float lo, float hi) {
    uint32_t r;
    asm("cvt.rn.f16x2.f32 %0, %1, %2;" : "=r"(r) : "f"(hi), "f"(lo));
    return r;
}

#define CP_ASYNC16(dst, src) \
    asm volatile("cp.async.cg.shared.global [%0], [%1], 16;" :: "r"(dst), "l"(src) : "memory")
#define CP_COMMIT() asm volatile("cp.async.commit_group;" ::: "memory")
#define CP_WAIT(n)  asm volatile("cp.async.wait_group %0;" :: "n"(n) : "memory")

__device__ __forceinline__ void mma_f16(float* c, const uint32_t* a, uint32_t b0, uint32_t b1) {
    asm volatile(
        "mma.sync.aligned.m16n8k16.row.col.f32.f16.f16.f32 "
        "{%0, %1, %2, %3}, {%4, %5, %6, %7}, {%8, %9}, {%0, %1, %2, %3};"
        : "+f"(c[0]), "+f"(c[1]), "+f"(c[2]), "+f"(c[3])
        : "r"(a[0]), "r"(a[1]), "r"(a[2]), "r"(a[3]), "r"(b0), "r"(b1));
}

// ---------------------------------------------------------------------------
// Kernel 1: per-row inverse L2 norm (exact fp32), both matrices.
// ---------------------------------------------------------------------------
__global__ void inv_norm_kernel(const float* __restrict__ t, const float* __restrict__ s) {
    int gw = (blockIdx.x * blockDim.x + threadIdx.x) >> 5;
    int lane = threadIdx.x & 31;
    if (gw >= 2 * NROWS) return;

    const float* src = (gw < NROWS) ? t : s;
    float* invp      = (gw < NROWS) ? g_inv_t : g_inv_s;
    int row = (gw < NROWS) ? gw : gw - NROWS;

    const float4* rin = (const float4*)(src + (size_t)row * KDIM);
    float acc = 0.f;
#pragma unroll
    for (int i = 0; i < (KDIM / 4) / 32; i++) {
        float4 v = rin[lane + i * 32];
        acc = fmaf(v.x, v.x, acc);
        acc = fmaf(v.y, v.y, acc);
        acc = fmaf(v.z, v.z, acc);
        acc = fmaf(v.w, v.w, acc);
    }
#pragma unroll
    for (int o = 16; o > 0; o >>= 1)
        acc += __shfl_xor_sync(0xffffffffu, acc, o);
    if (lane == 0)
        invp[row] = rsqrtf(acc);   // norms ~32: eps clamp in ref never binds
}

// ---------------------------------------------------------------------------
// Kernel 2: fp16 fragment-order permute. One thread = one output uint4.
// ---------------------------------------------------------------------------
__global__ void permute_kernel(const float* __restrict__ t, const float* __restrict__ s) {
    int gg = blockIdx.x * blockDim.x + threadIdx.x;
    const int per_mat = NR16 * NKG * 32;        // 524288
    int mat = gg >= per_mat;
    int idx = mat ? gg - per_mat : gg;

    int R    = idx >> 11;          // /2048
    int Kg   = (idx >> 5) & 63;
    int lane = idx & 31;
    int g  = lane >> 2;
    int tk = lane & 3;

    const float* src = mat ? s : t;
    uint4* dst       = mat ? g_pb : g_pa;

    const float* r0 = src + (size_t)(16 * R + g) * KDIM + 16 * Kg + 2 * tk;
    const float* r1 = r0 + 8 * KDIM;

    float2 v00 = *(const float2*)(r0);
    float2 v10 = *(const float2*)(r1);
    float2 v01 = *(const float2*)(r0 + 8);
    float2 v11 = *(const float2*)(r1 + 8);

    uint4 o;
    o.x = pack_h2(v00.x, v00.y);
    o.y = pack_h2(v10.x, v10.y);
    o.z = pack_h2(v01.x, v01.y);
    o.w = pack_h2(v11.x, v11.y);
    dst[idx] = o;
}

// ---------------------------------------------------------------------------
// Kernel 3: fp16 mma.sync GEMM with fused cosine epilogue.
// CTA 128x128x32, 8 warps (2 m x 4 n), warp tile 64x32, m16n8k16 fragments.
// 4-stage cp.async pipeline over fragment-ordered operands (LDS.128 only).
// ---------------------------------------------------------------------------
__global__ void __launch_bounds__(256, 2)
cosine_mma_kernel(float* __restrict__ C) {
    extern __shared__ uint4 smem4[];
    const uint32_t sbase = smem_u32(smem4);

    const int tid  = threadIdx.x;
    const int wid  = tid >> 5;
    const int lane = tid & 31;
    const int g  = lane >> 2;
    const int tk = lane & 3;

    const int wm = wid & 1;        // 2 m-warps
    const int wn = wid >> 1;       // 4 n-warps

    const int R0 = blockIdx.y * 8;   // 16-row groups of A
    const int N0 = blockIdx.x * 8;   // 16-row groups of B
    const int row0 = blockIdx.y * BM;
    const int col0 = blockIdx.x * BN;

    const char* Ap = (const char*)g_pa;
    const char* Bp = (const char*)g_pb;

    float acc[4][4][4];
#pragma unroll
    for (int i = 0; i < 4; i++)
#pragma unroll
        for (int j = 0; j < 4; j++)
#pragma unroll
            for (int q = 0; q < 4; q++)
                acc[i][j][q] = 0.f;

    // stage = 1024 chunks of 16B: [0,512) A (blk=r16*2+kg), [512,1024) B
    auto issue_stage = [&](int s, int kit) {
        uint32_t dst0 = sbase + (uint32_t)s * STAGE_BYTES;
#pragma unroll
        for (int i = 0; i < 4; i++) {
            int c    = tid + i * 256;
            int side = c >> 9;
            int blk  = (c >> 5) & 15;
            int lc   = c & 31;
            int grp  = (side ? N0 : R0) + (blk >> 1);
            int kg   = kit * 2 + (blk & 1);
            const char* src = (side ? Bp : Ap) + (((size_t)grp * NKG + kg) * 32 + lc) * 16;
            CP_ASYNC16(dst0 + (uint32_t)c * 16u, src);
        }
    };

#pragma unroll
    for (int s = 0; s < STAGES - 1; s++) {
        issue_stage(s, s);
        CP_COMMIT();
    }

    for (int it = 0; it < KITERS; it++) {
        CP_WAIT(STAGES - 2);
        __syncthreads();

        int nx = it + STAGES - 1;
        if (nx < KITERS) issue_stage(nx & (STAGES - 1), nx);
        CP_COMMIT();

        const uint4* stg = smem4 + (it & (STAGES - 1)) * 1024;

#pragma unroll
        for (int kg = 0; kg < 2; kg++) {
            uint4 af[4];
#pragma unroll
            for (int mt = 0; mt < 4; mt++)
                af[mt] = stg[((wm * 4 + mt) * 2 + kg) * 32 + lane];
            uint4 bf[2];
#pragma unroll
            for (int p = 0; p < 2; p++)
                bf[p] = stg[512 + ((wn * 2 + p) * 2 + kg) * 32 + lane];

#pragma unroll
            for (int mt = 0; mt < 4; mt++) {
                const uint32_t* a = (const uint32_t*)&af[mt];
                mma_f16(acc[mt][0], a, bf[0].x, bf[0].z);
                mma_f16(acc[mt][1], a, bf[0].y, bf[0].w);
                mma_f16(acc[mt][2], a, bf[1].x, bf[1].z);
                mma_f16(acc[mt][3], a, bf[1].y, bf[1].w);
            }
        }
        __syncthreads();
    }

    // ---- epilogue: fold inverse norms, float2 stores ----
    const int mbase = wm * 64;
    const int nbase = wn * 32;
#pragma unroll
    for (int mt = 0; mt < 4; mt++) {
        const int r0 = row0 + mbase + mt * 16 + g;
        const int r1 = r0 + 8;
        const float ia0 = g_inv_t[r0];
        const float ia1 = g_inv_t[r1];
#pragma unroll
        for (int nt = 0; nt < 4; nt++) {
            const int col = col0 + nbase + nt * 8 + 2 * tk;
            const float ib0 = g_inv_s[col];
            const float ib1 = g_inv_s[col + 1];
            float2 o0, o1;
            o0.x = acc[mt][nt][0] * ia0 * ib0;
            o0.y = acc[mt][nt][1] * ia0 * ib1;
            o1.x = acc[mt][nt][2] * ia1 * ib0;
            o1.y = acc[mt][nt][3] * ia1 * ib1;
            *(float2*)(C + (size_t)r0 * NCOLS + col) = o0;
            *(float2*)(C + (size_t)r1 * NCOLS + col) = o1;
        }
    }
}

// ---------------------------------------------------------------------------
extern "C" void kernel_launch(void* const* d_in, const int* in_sizes, int n_in,
                              void* d_out, int out_size) {
    const float* target = (const float*)d_in[0];
    const float* ss     = (const float*)d_in[1];
    float* out          = (float*)d_out;

    inv_norm_kernel<<<(2 * NROWS) / 8, 256>>>(target, ss);
    permute_kernel<<<(2 * NR16 * NKG * 32) / 256, 256>>>(target, ss);

    cudaFuncSetAttribute(cosine_mma_kernel, cudaFuncAttributeMaxDynamicSharedMemorySize, SMEM_BYTES);
    dim3 grid(NCOLS / BN, NROWS / BM);   // 32 x 32
    cosine_mma_kernel<<<grid, 256, SMEM_BYTES>>>(out);
}